// round 8
// baseline (speedup 1.0000x reference)
#include <cuda_runtime.h>

// PoseLSTM v7: warp-per-layer, register recurrence, chunked SMEM handoff.
//   block = 320 threads = 10 warps; warp w = layer w; lane = (e,u), e<3, u<10
//   lane owns all 4 gate rows of unit u, k-packed: 40 u64 weight regs
//   own-h recurrence: pure registers + 10 intra-warp shfl.idx per step
//   layer l -> l+1 handoff: chunks of C=8 steps, double-buffered SMEM,
//   ONE __syncthreads per super-step (137 total vs 1034)
//   sigmoid folded: rows i,f,o and biases pre-scaled by 0.5; s=0.5+0.5*tanh

#define T_ 1024
#define B_ 1024
#define L_ 10
#define H_ 10
#define C_ 8
#define NCH (T_ / C_)          // 128 chunks
#define NTH 320
#define ROWF 22                // float stride per element row (bank-clean, 8B-aligned)
#define TCF (3 * ROWF)         // 66 floats per (layer, tc)

typedef unsigned long long u64;

__device__ __forceinline__ u64 pk2(float lo, float hi) {
    u64 r; asm("mov.b64 %0, {%1,%2};" : "=l"(r) : "f"(lo), "f"(hi)); return r;
}
__device__ __forceinline__ void upk2(u64 v, float& lo, float& hi) {
    asm("mov.b64 {%0,%1}, %2;" : "=f"(lo), "=f"(hi) : "l"(v));
}
__device__ __forceinline__ u64 fma2(u64 a, u64 b, u64 c) {
    u64 d; asm("fma.rn.f32x2 %0, %1, %2, %3;" : "=l"(d) : "l"(a), "l"(b), "l"(c));
    return d;
}
__device__ __forceinline__ float tanhap(float x) {
    float r; asm("tanh.approx.f32 %0, %1;" : "=f"(r) : "f"(x)); return r;
}

__global__ __launch_bounds__(NTH)
void lstm_pipe7(const float* __restrict__ x,   // (T,B,H)
                const float* __restrict__ hp,  // (L,B,H)
                const float* __restrict__ cp,  // (L,B,H)
                const float* __restrict__ Wih, // (L,4H,H)
                const float* __restrict__ Whh, // (L,4H,H)
                const float* __restrict__ bih, // (L,4H)
                const float* __restrict__ bhh, // (L,4H)
                float* __restrict__ out)       // ys ++ hn ++ cn
{
    // sb[parity][layer][tc][3*22]: inputs-from-below for 'layer', chunk-staged.
    __shared__ __align__(16) float sb[2][L_][C_][TCF];   // 42240 B

    const int tid  = threadIdx.x;
    const int l    = tid >> 5;                // warp = layer
    const int lane = tid & 31;
    const int e    = lane / 10;               // 0..2 valid; 3 for lanes 30,31
    const int u    = lane % 10;
    const int eC   = (lane < 30) ? e : 0;     // clamped for safe addressing
    const int b    = blockIdx.x * 3 + e;
    const bool mem_ok = (lane < 30) && (b < B_);
    const int q0   = eC * 10;                 // shfl source base for this element

    // ---- k-packed register-stationary weights (rows i,f,g,o of unit u) ----
    u64 wi[4][5], wh[4][5];
    float bias[4];
#pragma unroll
    for (int g = 0; g < 4; ++g) {
        const int row = l * 40 + g * 10 + u;
        const float scl = (g == 2) ? 1.0f : 0.5f;     // fold sigmoid 0.5
        const float* WiP = Wih + row * 10;
        const float* WhP = Whh + row * 10;
#pragma unroll
        for (int m = 0; m < 5; ++m) {
            wi[g][m] = pk2(scl * __ldg(WiP + 2 * m), scl * __ldg(WiP + 2 * m + 1));
            wh[g][m] = pk2(scl * __ldg(WhP + 2 * m), scl * __ldg(WhP + 2 * m + 1));
        }
        bias[g] = scl * (bih[row] + bhh[row]);
    }

    // ---- init state (register-resident recurrence) ----
    float h = 0.0f, c = 0.0f;
    if (mem_ok) {
        h = hp[(l * B_ + b) * H_ + u];
        c = cp[(l * B_ + b) * H_ + u];
    }

    // ---- initial x chunk (chunk 0) into sb[0][0] ----
    if (l == 0 && mem_ok) {
#pragma unroll
        for (int tc = 0; tc < C_; ++tc)
            sb[0][0][tc][e * ROWF + u] = x[((size_t)tc * B_ + b) * H_ + u];
    }

    const size_t base_hn = (size_t)T_ * B_ * H_;
    const size_t base_cn = base_hn + (size_t)L_ * B_ * H_;

    // ---- super-step loop: one barrier per chunk ----
    for (int k = 0; k < NCH + L_ - 1; ++k) {
        __syncthreads();
        const int ch = k - l;
        if ((unsigned)ch >= (unsigned)NCH) continue;   // warp-uniform skip
        const int p = k & 1;

        const float* rbuf = &sb[p][l][0][0];
        float* wbuf = (l < L_ - 1) ? &sb[p ^ 1][l + 1][0][0] : &sb[p ^ 1][l][0][0];
        const bool lastCh = (ch == NCH - 1);
        const bool pfx = (l == 0) && !lastCh;          // prefetch next x chunk

#pragma unroll
        for (int tc = 0; tc < C_; ++tc) {
            // layer-0: stream next chunk's x (one element per tc iteration)
            if (pfx && mem_ok) {
                float xv = x[((size_t)((ch + 1) * C_ + tc) * B_ + b) * H_ + u];
                sb[p ^ 1][0][tc][e * ROWF + u] = xv;
            }

            // ---- gate pre-activations: 40 k-packed FMA2 ----
            const u64* q = reinterpret_cast<const u64*>(rbuf + tc * TCF + eC * ROWF);
            u64 ai = pk2(bias[0], 0.0f);
            u64 af = pk2(bias[1], 0.0f);
            u64 ag = pk2(bias[2], 0.0f);
            u64 ao = pk2(bias[3], 0.0f);
#pragma unroll
            for (int m = 0; m < 5; ++m) {              // input-from-below part
                u64 z = q[m];
                ai = fma2(wi[0][m], z, ai);
                af = fma2(wi[1][m], z, af);
                ag = fma2(wi[2][m], z, ag);
                ao = fma2(wi[3][m], z, ao);
            }
            u64 ph[5];                                  // own-h pairs via shfl
#pragma unroll
            for (int m = 0; m < 5; ++m)
                ph[m] = pk2(__shfl_sync(0xFFFFFFFFu, h, q0 + 2 * m),
                            __shfl_sync(0xFFFFFFFFu, h, q0 + 2 * m + 1));
#pragma unroll
            for (int m = 0; m < 5; ++m) {
                ai = fma2(wh[0][m], ph[m], ai);
                af = fma2(wh[1][m], ph[m], af);
                ag = fma2(wh[2][m], ph[m], ag);
                ao = fma2(wh[3][m], ph[m], ao);
            }
            float pi, pih, pf, pfh, pg, pgh, po, poh;
            upk2(ai, pi, pih); upk2(af, pf, pfh);
            upk2(ag, pg, pgh); upk2(ao, po, poh);
            pi += pih; pf += pfh; pg += pgh; po += poh;

            // ---- activations (0.5 folded) + cell ----
            const float gi = fmaf(0.5f, tanhap(pi), 0.5f);
            const float gf = fmaf(0.5f, tanhap(pf), 0.5f);
            const float gg = tanhap(pg);
            const float go = fmaf(0.5f, tanhap(po), 0.5f);
            c = fmaf(gf, c, gi * gg);
            h = go * tanhap(c);

            // ---- handoff / outputs ----
            const int t = ch * C_ + tc;
            if (l < L_ - 1) {
                if (lane < 30)
                    wbuf[tc * TCF + e * ROWF + u] = h;
            } else if (mem_ok) {
                out[((size_t)t * B_ + b) * H_ + u] = h;
            }
            if (lastCh && tc == C_ - 1 && mem_ok) {
                out[base_hn + ((size_t)l * B_ + b) * H_ + u] = h;
                out[base_cn + ((size_t)l * B_ + b) * H_ + u] = c;
            }
        }
    }
}

extern "C" void kernel_launch(void* const* d_in, const int* in_sizes, int n_in,
                              void* d_out, int out_size) {
    const float* x   = (const float*)d_in[0];
    const float* hp  = (const float*)d_in[1];
    const float* cp  = (const float*)d_in[2];
    const float* Wih = (const float*)d_in[3];
    const float* Whh = (const float*)d_in[4];
    const float* bih = (const float*)d_in[5];
    const float* bhh = (const float*)d_in[6];
    float* out = (float*)d_out;

    dim3 grid((B_ + 2) / 3);   // 342 blocks, 3 batch elems each
    dim3 block(NTH);           // 320 threads = 10 warps (one per layer)
    lstm_pipe7<<<grid, block>>>(x, hp, cp, Wih, Whh, bih, bhh, out);
}

// round 9
// speedup vs baseline: 1.4959x; 1.4959x over previous
#include <cuda_runtime.h>

// PoseLSTM v8: v5/v6 gate-pair math, 2 elems/thread, TWO blocks per SM.
//   256 blocks x 400 threads, __launch_bounds__(400,2) -> single wave,
//   two independent barrier domains per SM (issue overlap across blocks).
//   thread = (l, u, eh, gp): 2 gate rows (i,f | g,o) for elements eh and eh+2
//   20x fma.rn.f32x2 per element, bias folded into first FMA2, mul2 chain start
//   pair exchange: 2 shfl.xor(1) + selects; 1 syncthreads/step, parity unrolled

#define T_ 1024
#define B_ 1024
#define L_ 10
#define H_ 10
#define NB 4
#define NTH 400

typedef unsigned long long u64;

__device__ __forceinline__ u64 pk2(float lo, float hi) {
    u64 r; asm("mov.b64 %0, {%1,%2};" : "=l"(r) : "f"(lo), "f"(hi)); return r;
}
__device__ __forceinline__ void upk2(u64 v, float& lo, float& hi) {
    asm("mov.b64 {%0,%1}, %2;" : "=f"(lo), "=f"(hi) : "l"(v));
}
__device__ __forceinline__ u64 fma2(u64 a, u64 b, u64 c) {
    u64 d; asm("fma.rn.f32x2 %0, %1, %2, %3;" : "=l"(d) : "l"(a), "l"(b), "l"(c));
    return d;
}
__device__ __forceinline__ u64 mul2(u64 a, u64 b) {
    u64 d; asm("mul.rn.f32x2 %0, %1, %2;" : "=l"(d) : "l"(a), "l"(b));
    return d;
}
__device__ __forceinline__ u64 add2(u64 a, u64 b) {
    u64 d; asm("add.rn.f32x2 %0, %1, %2;" : "=l"(d) : "l"(a), "l"(b));
    return d;
}
__device__ __forceinline__ float tanhap(float x) {
    float r; asm("tanh.approx.f32 %0, %1;" : "=f"(r) : "f"(x)); return r;
}

// matvec for one element: 2 gate rows, 4 chains, bias pre-folded
__device__ __forceinline__ void matvec2(const ulonglong2* zz,
                                        const u64* wA, const u64* wB,
                                        u64 biasA2, u64 biasB2,
                                        float& pA, float& pB) {
    ulonglong2 v0 = zz[0], v1 = zz[1], v2 = zz[2], v3 = zz[3], v4 = zz[4];
    u64 a  = fma2(wA[0], v0.x, biasA2);
    u64 a_ = mul2(wA[1], v0.y);
    u64 b  = fma2(wB[0], v0.x, biasB2);
    u64 b_ = mul2(wB[1], v0.y);
    a  = fma2(wA[2], v1.x, a);  a_ = fma2(wA[3], v1.y, a_);
    b  = fma2(wB[2], v1.x, b);  b_ = fma2(wB[3], v1.y, b_);
    a  = fma2(wA[4], v2.x, a);  a_ = fma2(wA[5], v2.y, a_);
    b  = fma2(wB[4], v2.x, b);  b_ = fma2(wB[5], v2.y, b_);
    a  = fma2(wA[6], v3.x, a);  a_ = fma2(wA[7], v3.y, a_);
    b  = fma2(wB[6], v3.x, b);  b_ = fma2(wB[7], v3.y, b_);
    a  = fma2(wA[8], v4.x, a);  a_ = fma2(wA[9], v4.y, a_);
    b  = fma2(wB[8], v4.x, b);  b_ = fma2(wB[9], v4.y, b_);
    u64 sA = add2(a, a_), sB = add2(b, b_);
    float lo, hi;
    upk2(sA, lo, hi); pA = lo + hi;
    upk2(sB, lo, hi); pB = lo + hi;
}

__global__ __launch_bounds__(NTH, 2)
void lstm_pipe8(const float* __restrict__ x,   // (T,B,H)
                const float* __restrict__ hp,  // (L,B,H)
                const float* __restrict__ cp,  // (L,B,H)
                const float* __restrict__ Wih, // (L,4H,H)
                const float* __restrict__ Whh, // (L,4H,H)
                const float* __restrict__ bih, // (L,4H)
                const float* __restrict__ bhh, // (L,4H)
                float* __restrict__ out)       // ys ++ hn ++ cn
{
    // z[buf][layer][elem(4)][24]: 0..9 input-from-below, 10..19 own h.
    __shared__ __align__(16) float z[2][L_ + 1][NB][24];   // 8448 B

    const int tid = threadIdx.x;
    const int l   = tid / 40;
    const int r   = tid % 40;          // u*4 + eh*2 + gp
    const int u   = r >> 2;
    const int eh  = (r >> 1) & 1;      // element slots eh and eh+2
    const int gp  = r & 1;             // 0: (i,f)   1: (g~,o)
    const int e2  = eh + 2;
    const int b   = blockIdx.x * NB + eh;
    const int b2  = b + 2;

    // ---- k-packed register-stationary weights, sigmoid 0.5 folded ----
    const int rowA = l * 40 + gp * 20 + u;    // i (gp0) or g~ (gp1)
    const int rowB = rowA + 10;               // f (gp0) or o  (gp1)
    const float sclA = gp ? 1.0f : 0.5f;
    u64 wA[10], wB[10];
    {
        const float* WiA = Wih + rowA * 10; const float* WhA = Whh + rowA * 10;
        const float* WiB = Wih + rowB * 10; const float* WhB = Whh + rowB * 10;
#pragma unroll
        for (int k = 0; k < 5; ++k) {
            wA[k]     = pk2(sclA * __ldg(WiA + 2 * k), sclA * __ldg(WiA + 2 * k + 1));
            wA[5 + k] = pk2(sclA * __ldg(WhA + 2 * k), sclA * __ldg(WhA + 2 * k + 1));
            wB[k]     = pk2(0.5f * __ldg(WiB + 2 * k), 0.5f * __ldg(WiB + 2 * k + 1));
            wB[5 + k] = pk2(0.5f * __ldg(WhB + 2 * k), 0.5f * __ldg(WhB + 2 * k + 1));
        }
    }
    const u64 biasA2 = pk2(sclA * (bih[rowA] + bhh[rowA]), 0.0f);
    const u64 biasB2 = pk2(0.5f * (bih[rowB] + bhh[rowB]), 0.0f);
    const float cAa = gp ? 0.0f : 0.5f;   // act A: gp0 sigmoid, gp1 tanh
    const float cBa = gp ? 1.0f : 0.5f;

    // ---- init state ----
    float c  = cp[(l * B_ + b ) * H_ + u];
    float c2 = cp[(l * B_ + b2) * H_ + u];
    if (gp == 0) {
        z[l & 1][l][eh][10 + u] = hp[(l * B_ + b ) * H_ + u];
        z[l & 1][l][e2][10 + u] = hp[(l * B_ + b2) * H_ + u];
    }
    const bool isLdr = (l == 0 && gp == 0);
    if (isLdr) {
        z[0][0][eh][u] = x[(size_t)b  * H_ + u];
        z[0][0][e2][u] = x[(size_t)b2 * H_ + u];
    }

    const size_t base_hn = (size_t)T_ * B_ * H_;
    const size_t base_cn = base_hn + (size_t)L_ * B_ * H_;

    // ---- wavefront main loop, parity-unrolled ----
    for (int s0 = 0; s0 < 1034; s0 += 2) {
#pragma unroll
        for (int par = 0; par < 2; ++par) {
            const int scur = s0 + par;
            const int t = scur - l;
            const bool act = ((unsigned)t < (unsigned)T_);

            float xl, xl2;
            const bool ldrGo = isLdr && (scur + 1 < T_);
            if (ldrGo) {
                xl  = x[((size_t)(scur + 1) * B_ + b ) * H_ + u];
                xl2 = x[((size_t)(scur + 1) * B_ + b2) * H_ + u];
            }

            __syncthreads();   // step s-1 z-writes -> step s z-reads

            const ulonglong2* zzA =
                reinterpret_cast<const ulonglong2*>(&z[par][l][eh][0]);
            const ulonglong2* zzB =
                reinterpret_cast<const ulonglong2*>(&z[par][l][e2][0]);

            float pA, pB, qA, qB;
            matvec2(zzA, wA, wB, biasA2, biasB2, pA, pB);
            matvec2(zzB, wA, wB, biasA2, biasB2, qA, qB);

            // ---- activations ----
            float vA  = fmaf(cBa,  tanhap(pA), cAa);
            float vB  = fmaf(0.5f, tanhap(pB), 0.5f);
            float vA2 = fmaf(cBa,  tanhap(qA), cAa);
            float vB2 = fmaf(0.5f, tanhap(qB), 0.5f);

            // ---- pair exchange + cell update ----
            float Ao  = __shfl_xor_sync(0xFFFFFFFFu, vA, 1);
            float Bo  = __shfl_xor_sync(0xFFFFFFFFu, vB, 1);
            float Ao2 = __shfl_xor_sync(0xFFFFFFFFu, vA2, 1);
            float Bo2 = __shfl_xor_sync(0xFFFFFFFFu, vB2, 1);
            float F  = gp ? Bo  : vB;
            float O  = gp ? vB  : Bo;
            float F2 = gp ? Bo2 : vB2;
            float O2 = gp ? vB2 : Bo2;
            if (act) {
                c  = fmaf(F,  c,  vA  * Ao);
                c2 = fmaf(F2, c2, vA2 * Ao2);
            }
            float h  = O  * tanhap(c);
            float h2 = O2 * tanhap(c2);

            // ---- h handoff / outputs ----
            if (act) {
                if (gp == 0) {
                    z[par ^ 1][l][eh][10 + u] = h;
                    z[par ^ 1][l][e2][10 + u] = h2;
                } else if (l < L_ - 1) {
                    z[par ^ 1][l + 1][eh][u] = h;
                    z[par ^ 1][l + 1][e2][u] = h2;
                } else {
                    out[((size_t)t * B_ + b ) * H_ + u] = h;
                    out[((size_t)t * B_ + b2) * H_ + u] = h2;
                }
                if (t == T_ - 1) {
                    if (gp == 0) {
                        out[base_hn + ((size_t)l * B_ + b ) * H_ + u] = h;
                        out[base_hn + ((size_t)l * B_ + b2) * H_ + u] = h2;
                    } else {
                        out[base_cn + ((size_t)l * B_ + b ) * H_ + u] = c;
                        out[base_cn + ((size_t)l * B_ + b2) * H_ + u] = c2;
                    }
                }
            }
            if (ldrGo) {
                z[par ^ 1][0][eh][u] = xl;
                z[par ^ 1][0][e2][u] = xl2;
            }
        }
    }
}

extern "C" void kernel_launch(void* const* d_in, const int* in_sizes, int n_in,
                              void* d_out, int out_size) {
    const float* x   = (const float*)d_in[0];
    const float* hp  = (const float*)d_in[1];
    const float* cp  = (const float*)d_in[2];
    const float* Wih = (const float*)d_in[3];
    const float* Whh = (const float*)d_in[4];
    const float* bih = (const float*)d_in[5];
    const float* bhh = (const float*)d_in[6];
    float* out = (float*)d_out;

    dim3 grid(B_ / NB);   // 256 blocks; 2 blocks/SM -> single wave on 128 SMs
    dim3 block(NTH);      // 400 threads = 12.5 warps
    lstm_pipe8<<<grid, block>>>(x, hp, cp, Wih, Whh, bih, bhh, out);
}